// round 11
// baseline (speedup 1.0000x reference)
#include <cuda_runtime.h>
#include <math.h>

// ---------------------------------------------------------------------------
// YoloV1Loss — R11 = R10 + Programmatic Dependent Launch.
// K1 (unchanged, best known): cp.async.cg full-row staging, 128thr/128rows,
//     7 blocks/SM; triggers griddepcontrol.launch_dependents after publishing
//     its meta record so K2 can launch/ramp during K1's tail wave.
// K2 (unchanged logic): griddepcontrol.wait, then coalesced smem finalize.
// PDL degrades safely to plain stream order if not honored.
// ---------------------------------------------------------------------------

#define TPB   128
#define RPT   128
#define MAXT  8192
#define NCLS  20
#define FTPB  1024

__device__ float4 g_meta[MAXT];            // (csum, noobj, count, 0)
__device__ int    g_cnt[MAXT];
__device__ float  g_contrib[MAXT * RPT];   // rank-compacted per tile

// ---------------- K1: main pass ----------------
__global__ void __launch_bounds__(TPB) yolo_main(const float* __restrict__ p,
                                                 const float* __restrict__ t,
                                                 int nrows) {
    extern __shared__ float smem[];
    float* ps  = smem;                 // TPB*30 floats
    float* tsd = smem + TPB * 30;      // TPB*30 floats
    __shared__ int   wtot[TPB / 32];
    __shared__ float wredN[TPB / 32];
    __shared__ float wredC[TPB / 32];

    const int tid  = threadIdx.x;
    const int bid  = blockIdx.x;
    const int row0 = bid * RPT;
    const int lane = tid & 31;
    const int wid  = tid >> 5;
    const int rows = min(RPT, nrows - row0);
    const int n16  = (rows * 30) >> 2;           // 16B units
    const size_t base = (size_t)row0 * 30;

    // cp.async staging: fire-and-forget, ~30 copies in flight per thread
    {
        const float* pg = p + base;
        const float* tg = t + base;
        const unsigned ap = (unsigned)__cvta_generic_to_shared(ps);
        const unsigned at = (unsigned)__cvta_generic_to_shared(tsd);
        for (int i = tid; i < n16; i += TPB) {
            asm volatile("cp.async.cg.shared.global [%0], [%1], 16;\n"
                         :: "r"(ap + i * 16), "l"(pg + i * 4));
            asm volatile("cp.async.cg.shared.global [%0], [%1], 16;\n"
                         :: "r"(at + i * 16), "l"(tg + i * 4));
        }
        for (int i = (n16 << 2) + tid; i < rows * 30; i += TPB) {  // odd tail
            ps[i]  = pg[i];
            tsd[i] = tg[i];
        }
        asm volatile("cp.async.commit_group;\n" ::: "memory");
        asm volatile("cp.async.wait_group 0;\n" ::: "memory");
    }
    __syncthreads();

    const bool inrange = (tid < rows);
    const float* pr = ps  + tid * 30;
    const float* tr = tsd + tid * 30;

    const float conf = inrange ? tr[4] : -1.0f;
    const bool  cm   = (conf == 1.0f);

    // in-block inclusive rank of coord rows
    const unsigned bal = __ballot_sync(0xffffffffu, cm);
    unsigned le_mask;
    asm("mov.u32 %0, %%lanemask_le;" : "=r"(le_mask));
    const int inc = __popc(bal & le_mask);
    if (lane == 31) wtot[wid] = __popc(bal);
    __syncthreads();
    int woff = 0, ctot = 0;
#pragma unroll
    for (int i = 0; i < TPB / 32; i++) {
        const int c = wtot[i];
        if (i < wid) woff += c;
        ctot += c;
    }

    // noobj term
    float nv = 0.0f;
    if (inrange && conf == 0.0f) {
        const float d0 = pr[4] - tr[4];
        const float d1 = pr[9] - tr[9];
        nv = 0.5f * (d0 * d0 + d1 * d1);
    }

    // coord term (global gate resolved in K2)
    float cv = 0.0f;
    if (cm) {
        const float C = 1.0f / 7.0f;
        const float tb0 = tr[0] * tr[0], tb1 = tr[1] * tr[1];
        const float tb2 = tr[2] * tr[2], tb3 = tr[3] * tr[3];
        const float tax = tb0 * C - tb2, tay = tb1 * C - tb3;
        const float tbx = tax * C + tb2, tby = tay * C + tb3;
        const float at2 = (tbx - tax) * (tby - tay);

        float iou0 = 0.0f, iou1 = 0.0f;
#pragma unroll
        for (int b = 0; b < 2; b++) {
            const float x = pr[b * 5 + 0], y = pr[b * 5 + 1];
            const float w = pr[b * 5 + 2], h = pr[b * 5 + 3];
            const float ax = x * C - w,  ay = y * C - h;
            const float bx = ax * C + w, by = ay * C + h;
            const float iw = fmaxf(fminf(bx, tbx) - fmaxf(ax, tax), 0.0f);
            const float ih = fmaxf(fminf(by, tby) - fmaxf(ay, tay), 0.0f);
            const float inter = iw * ih;
            const float ap2 = (bx - ax) * (by - ay);
            const float iou = inter / (ap2 + at2 - inter);
            if (b == 0) iou0 = iou; else iou1 = iou;
        }
        int idx;
        if (isnan(iou0))      idx = 0;   // numpy argmax: NaN wins, first occ.
        else if (isnan(iou1)) idx = 1;
        else                  idx = (iou1 > iou0) ? 1 : 0;

        const int ob = idx * 5;
        const float s0 = pr[ob + 0] - tr[0];
        const float s1 = pr[ob + 1] - tr[1];
        const float s2 = pr[ob + 2] - tr[2];
        const float s3 = pr[ob + 3] - tr[3];

        // class argmax from smem (first strict max) + paired p-select
        float best = tr[10];
        float clp  = pr[10];
#pragma unroll
        for (int j = 1; j < NCLS; j++) {
            const float v = tr[10 + j];
            const bool  u = (v > best);
            best = u ? v : best;
            clp  = u ? pr[10 + j] : clp;
        }
        const float clv = clp - 1.0f;

        cv = 5.0f * (s0 * s0 + s1 * s1 + s2 * s2 + s3 * s3 + 2.0f * clv * clv);
        g_contrib[bid * RPT + (woff + inc - 1)] = cv;
    }

    // block reductions: noobj + coord sums
#pragma unroll
    for (int o = 16; o > 0; o >>= 1) {
        nv += __shfl_down_sync(0xffffffffu, nv, o);
        cv += __shfl_down_sync(0xffffffffu, cv, o);
    }
    if (lane == 0) { wredN[wid] = nv; wredC[wid] = cv; }
    __syncthreads();
    if (tid == 0) {
        float sn = 0.0f, sc = 0.0f;
#pragma unroll
        for (int i = 0; i < TPB / 32; i++) { sn += wredN[i]; sc += wredC[i]; }
        g_meta[bid] = make_float4(sc, sn, __int_as_float(ctot), 0.0f);
        g_cnt[bid]  = ctot;
    }
    __syncthreads();   // meta store issued before trigger

    // PDL: allow the dependent finalize grid to launch now
    asm volatile("griddepcontrol.launch_dependents;" ::: "memory");
}

// ---------------- K2: finalize (PDL-gated, single block) ----------------
__global__ void __launch_bounds__(FTPB) yolo_finalize(float* __restrict__ out,
                                                      int nt) {
    // wait for ALL K1 blocks' pre-trigger writes to be visible
    asm volatile("griddepcontrol.wait;" ::: "memory");

    extern __shared__ int ismem[];
    int* scnt = ismem;          // nt ints
    int* spre = ismem + nt;     // nt ints

    const int tid  = threadIdx.x;
    const int lane = tid & 31;
    const int wid  = tid >> 5;

    // 1) coalesced strided load of counts into smem
    for (int i = tid; i < nt; i += FTPB) scnt[i] = g_cnt[i];
    __syncthreads();

    // 2) chunked prefix over smem counts
    const int CH = (nt + FTPB - 1) / FTPB;
    const int i0 = tid * CH;
    int lsum = 0;
    for (int k = 0; k < CH; k++) {
        const int i = i0 + k;
        if (i < nt) lsum += scnt[i];
    }
    int incs = lsum;
#pragma unroll
    for (int o = 1; o < 32; o <<= 1) {
        const int x = __shfl_up_sync(0xffffffffu, incs, o);
        if (lane >= o) incs += x;
    }
    const int ex = incs - lsum;

    __shared__ int ws[FTPB / 32];
    __shared__ int wsx[FTPB / 32 + 1];
    __shared__ int s_bb, s_take;
    if (tid == 0) { s_bb = -1; s_take = 0; }
    if (lane == 31) ws[wid] = incs;
    __syncthreads();
    if (wid == 0) {
        int v = ws[lane];
#pragma unroll
        for (int o = 1; o < 32; o <<= 1) {
            const int x = __shfl_up_sync(0xffffffffu, v, o);
            if (lane >= o) v += x;
        }
        wsx[lane + 1] = v;
        if (lane == 0) wsx[0] = 0;
    }
    __syncthreads();
    const int half = wsx[FTPB / 32] >> 1;      // n_obj // 2

    // 3) per-record exclusive prefixes (smem walk)
    {
        int pre = wsx[wid] + ex;
        for (int k = 0; k < CH; k++) {
            const int i = i0 + k;
            if (i < nt) { spre[i] = pre; pre += scnt[i]; }
        }
    }
    __syncthreads();

    // 4) one strided coalesced pass over meta
    double acc = 0.0;
    for (int i = tid; i < nt; i += FTPB) {
        const float4 m   = g_meta[i];
        const int    cnt = scnt[i];
        const int    pre = spre[i];
        acc += (double)m.y;                                // noobj always
        const int take = min(cnt, max(0, half - pre));
        if (take == cnt)        acc += (double)m.x;        // fully taken
        else if (take > 0)    { s_bb = i; s_take = take; } // unique boundary
    }
    __syncthreads();

    // 5) boundary partial (<=RPT floats)
    if (s_bb >= 0) {
        const float* cb = g_contrib + s_bb * RPT;
        for (int i = tid; i < s_take; i += FTPB) acc += (double)cb[i];
    }

    // 6) block reduce (double)
#pragma unroll
    for (int o = 16; o > 0; o >>= 1)
        acc += __shfl_down_sync(0xffffffffu, acc, o);
    __shared__ double sd[FTPB / 32];
    if (lane == 0) sd[wid] = acc;
    __syncthreads();
    if (tid == 0) {
        double s = 0.0;
#pragma unroll
        for (int i = 0; i < FTPB / 32; i++) s += sd[i];
        out[0] = (float)s;
    }
}

// ---------------------------------------------------------------------------
extern "C" void kernel_launch(void* const* d_in, const int* in_sizes, int n_in,
                              void* d_out, int out_size) {
    const float* p = (const float*)d_in[0];
    const float* t = (const float*)d_in[1];

    const int nrows = in_sizes[0] / 30;
    const int nt    = (nrows + RPT - 1) / RPT;          // 6272

    const int smem_main = 2 * TPB * 30 * (int)sizeof(float);   // 30720
    cudaFuncSetAttribute(yolo_main,
                         cudaFuncAttributeMaxDynamicSharedMemorySize,
                         smem_main);

    const int smem_fin = 2 * nt * (int)sizeof(int);             // 50176
    cudaFuncSetAttribute(yolo_finalize,
                         cudaFuncAttributeMaxDynamicSharedMemorySize,
                         smem_fin);

    yolo_main<<<nt, TPB, smem_main>>>(p, t, nrows);

    // finalize with Programmatic Dependent Launch (overlaps launch/ramp with
    // K1's tail wave; degrades safely to stream order if unhonored)
    cudaLaunchConfig_t cfg = {};
    cfg.gridDim          = dim3(1, 1, 1);
    cfg.blockDim         = dim3(FTPB, 1, 1);
    cfg.dynamicSmemBytes = smem_fin;
    cfg.stream           = 0;
    cudaLaunchAttribute attr[1];
    attr[0].id = cudaLaunchAttributeProgrammaticStreamSerialization;
    attr[0].val.programmaticStreamSerializationAllowed = 1;
    cfg.attrs    = attr;
    cfg.numAttrs = 1;
    float* outf = (float*)d_out;
    cudaLaunchKernelEx(&cfg, yolo_finalize, outf, nt);
}

// round 12
// speedup vs baseline: 1.0860x; 1.0860x over previous
#include <cuda_runtime.h>
#include <math.h>

// ---------------------------------------------------------------------------
// YoloV1Loss — R12 = R11 with TMA BULK staging in K1.
// Every prior K1 (LDG/smem, reg-stream, cp.async persistent, cp.async churn)
// measured 3.3-3.5 TB/s regardless of MLP/occupancy => request-stream quality
// suspect: 16B-interleaved p/t requests thrash DRAM pages. Fix: ONE
// cp.async.bulk (UBLKCP) per array per block (15360B contiguous, issued by a
// single thread, mbarrier completion) => long address-ordered bursts.
// K2 + PDL unchanged.
// ---------------------------------------------------------------------------

#define TPB   128
#define RPT   128
#define MAXT  8192
#define NCLS  20
#define FTPB  1024
#define TILE_BYTES (RPT * 30 * 4)     // 15360 per array

__device__ float4 g_meta[MAXT];            // (csum, noobj, count, 0)
__device__ int    g_cnt[MAXT];
__device__ float  g_contrib[MAXT * RPT];   // rank-compacted per tile

// ---------------- K1: main pass ----------------
__global__ void __launch_bounds__(TPB) yolo_main(const float* __restrict__ p,
                                                 const float* __restrict__ t,
                                                 int nrows) {
    extern __shared__ float smem[];
    float* ps  = smem;                 // RPT*30 floats
    float* tsd = smem + RPT * 30;      // RPT*30 floats
    __shared__ __align__(8) unsigned long long mbar;
    __shared__ int   wtot[TPB / 32];
    __shared__ float wredN[TPB / 32];
    __shared__ float wredC[TPB / 32];

    const int tid  = threadIdx.x;
    const int bid  = blockIdx.x;
    const int row0 = bid * RPT;
    const int lane = tid & 31;
    const int wid  = tid >> 5;
    const int rows = min(RPT, nrows - row0);
    const size_t base = (size_t)row0 * 30;

    if (rows == RPT) {
        // ---- TMA bulk staging: 2 contiguous 15360B transfers ----
        const unsigned mb = (unsigned)__cvta_generic_to_shared(&mbar);
        const unsigned ap = (unsigned)__cvta_generic_to_shared(ps);
        const unsigned at = (unsigned)__cvta_generic_to_shared(tsd);
        if (tid == 0) {
            asm volatile("mbarrier.init.shared.b64 [%0], 1;"
                         :: "r"(mb) : "memory");
        }
        __syncthreads();
        if (tid == 0) {
            asm volatile("mbarrier.arrive.expect_tx.shared.b64 _, [%0], %1;"
                         :: "r"(mb), "r"(2 * TILE_BYTES) : "memory");
            asm volatile(
                "cp.async.bulk.shared::cta.global.mbarrier::complete_tx::bytes"
                " [%0], [%1], %2, [%3];"
                :: "r"(ap), "l"(p + base), "r"(TILE_BYTES), "r"(mb) : "memory");
            asm volatile(
                "cp.async.bulk.shared::cta.global.mbarrier::complete_tx::bytes"
                " [%0], [%1], %2, [%3];"
                :: "r"(at), "l"(t + base), "r"(TILE_BYTES), "r"(mb) : "memory");
        }
        // all threads wait for completion (phase 0), acquire semantics
        {
            unsigned done;
            asm volatile(
                "{\n\t.reg .pred pd;\n\t"
                "mbarrier.try_wait.parity.acquire.cta.shared::cta.b64 pd, [%1], 0;\n\t"
                "selp.b32 %0, 1, 0, pd;\n\t}"
                : "=r"(done) : "r"(mb) : "memory");
            while (!done) {
                asm volatile(
                    "{\n\t.reg .pred pd;\n\t"
                    "mbarrier.try_wait.parity.acquire.cta.shared::cta.b64 pd, [%1], 0, 0x989680;\n\t"
                    "selp.b32 %0, 1, 0, pd;\n\t}"
                    : "=r"(done) : "r"(mb) : "memory");
            }
        }
    } else {
        // ---- tail fallback: plain staged loads ----
        for (int i = tid; i < rows * 30; i += TPB) {
            ps[i]  = p[base + i];
            tsd[i] = t[base + i];
        }
    }
    __syncthreads();

    const bool inrange = (tid < rows);
    const float* pr = ps  + tid * 30;
    const float* tr = tsd + tid * 30;

    const float conf = inrange ? tr[4] : -1.0f;
    const bool  cm   = (conf == 1.0f);

    // in-block inclusive rank of coord rows
    const unsigned bal = __ballot_sync(0xffffffffu, cm);
    unsigned le_mask;
    asm("mov.u32 %0, %%lanemask_le;" : "=r"(le_mask));
    const int inc = __popc(bal & le_mask);
    if (lane == 31) wtot[wid] = __popc(bal);
    __syncthreads();
    int woff = 0, ctot = 0;
#pragma unroll
    for (int i = 0; i < TPB / 32; i++) {
        const int c = wtot[i];
        if (i < wid) woff += c;
        ctot += c;
    }

    // noobj term
    float nv = 0.0f;
    if (inrange && conf == 0.0f) {
        const float d0 = pr[4] - tr[4];
        const float d1 = pr[9] - tr[9];
        nv = 0.5f * (d0 * d0 + d1 * d1);
    }

    // coord term (global gate resolved in K2)
    float cv = 0.0f;
    if (cm) {
        const float C = 1.0f / 7.0f;
        const float tb0 = tr[0] * tr[0], tb1 = tr[1] * tr[1];
        const float tb2 = tr[2] * tr[2], tb3 = tr[3] * tr[3];
        const float tax = tb0 * C - tb2, tay = tb1 * C - tb3;
        const float tbx = tax * C + tb2, tby = tay * C + tb3;
        const float at2 = (tbx - tax) * (tby - tay);

        float iou0 = 0.0f, iou1 = 0.0f;
#pragma unroll
        for (int b = 0; b < 2; b++) {
            const float x = pr[b * 5 + 0], y = pr[b * 5 + 1];
            const float w = pr[b * 5 + 2], h = pr[b * 5 + 3];
            const float ax = x * C - w,  ay = y * C - h;
            const float bx = ax * C + w, by = ay * C + h;
            const float iw = fmaxf(fminf(bx, tbx) - fmaxf(ax, tax), 0.0f);
            const float ih = fmaxf(fminf(by, tby) - fmaxf(ay, tay), 0.0f);
            const float inter = iw * ih;
            const float ap2 = (bx - ax) * (by - ay);
            const float iou = inter / (ap2 + at2 - inter);
            if (b == 0) iou0 = iou; else iou1 = iou;
        }
        int idx;
        if (isnan(iou0))      idx = 0;   // numpy argmax: NaN wins, first occ.
        else if (isnan(iou1)) idx = 1;
        else                  idx = (iou1 > iou0) ? 1 : 0;

        const int ob = idx * 5;
        const float s0 = pr[ob + 0] - tr[0];
        const float s1 = pr[ob + 1] - tr[1];
        const float s2 = pr[ob + 2] - tr[2];
        const float s3 = pr[ob + 3] - tr[3];

        // class argmax from smem (first strict max) + paired p-select
        float best = tr[10];
        float clp  = pr[10];
#pragma unroll
        for (int j = 1; j < NCLS; j++) {
            const float v = tr[10 + j];
            const bool  u = (v > best);
            best = u ? v : best;
            clp  = u ? pr[10 + j] : clp;
        }
        const float clv = clp - 1.0f;

        cv = 5.0f * (s0 * s0 + s1 * s1 + s2 * s2 + s3 * s3 + 2.0f * clv * clv);
        g_contrib[bid * RPT + (woff + inc - 1)] = cv;
    }

    // block reductions: noobj + coord sums
#pragma unroll
    for (int o = 16; o > 0; o >>= 1) {
        nv += __shfl_down_sync(0xffffffffu, nv, o);
        cv += __shfl_down_sync(0xffffffffu, cv, o);
    }
    if (lane == 0) { wredN[wid] = nv; wredC[wid] = cv; }
    __syncthreads();
    if (tid == 0) {
        float sn = 0.0f, sc = 0.0f;
#pragma unroll
        for (int i = 0; i < TPB / 32; i++) { sn += wredN[i]; sc += wredC[i]; }
        g_meta[bid] = make_float4(sc, sn, __int_as_float(ctot), 0.0f);
        g_cnt[bid]  = ctot;
    }
    __syncthreads();

    // PDL trigger (neutral but harmless)
    asm volatile("griddepcontrol.launch_dependents;" ::: "memory");
}

// ---------------- K2: finalize (PDL-gated, single block) ----------------
__global__ void __launch_bounds__(FTPB) yolo_finalize(float* __restrict__ out,
                                                      int nt) {
    asm volatile("griddepcontrol.wait;" ::: "memory");

    extern __shared__ int ismem[];
    int* scnt = ismem;          // nt ints
    int* spre = ismem + nt;     // nt ints

    const int tid  = threadIdx.x;
    const int lane = tid & 31;
    const int wid  = tid >> 5;

    for (int i = tid; i < nt; i += FTPB) scnt[i] = g_cnt[i];
    __syncthreads();

    const int CH = (nt + FTPB - 1) / FTPB;
    const int i0 = tid * CH;
    int lsum = 0;
    for (int k = 0; k < CH; k++) {
        const int i = i0 + k;
        if (i < nt) lsum += scnt[i];
    }
    int incs = lsum;
#pragma unroll
    for (int o = 1; o < 32; o <<= 1) {
        const int x = __shfl_up_sync(0xffffffffu, incs, o);
        if (lane >= o) incs += x;
    }
    const int ex = incs - lsum;

    __shared__ int ws[FTPB / 32];
    __shared__ int wsx[FTPB / 32 + 1];
    __shared__ int s_bb, s_take;
    if (tid == 0) { s_bb = -1; s_take = 0; }
    if (lane == 31) ws[wid] = incs;
    __syncthreads();
    if (wid == 0) {
        int v = ws[lane];
#pragma unroll
        for (int o = 1; o < 32; o <<= 1) {
            const int x = __shfl_up_sync(0xffffffffu, v, o);
            if (lane >= o) v += x;
        }
        wsx[lane + 1] = v;
        if (lane == 0) wsx[0] = 0;
    }
    __syncthreads();
    const int half = wsx[FTPB / 32] >> 1;      // n_obj // 2

    {
        int pre = wsx[wid] + ex;
        for (int k = 0; k < CH; k++) {
            const int i = i0 + k;
            if (i < nt) { spre[i] = pre; pre += scnt[i]; }
        }
    }
    __syncthreads();

    double acc = 0.0;
    for (int i = tid; i < nt; i += FTPB) {
        const float4 m   = g_meta[i];
        const int    cnt = scnt[i];
        const int    pre = spre[i];
        acc += (double)m.y;                                // noobj always
        const int take = min(cnt, max(0, half - pre));
        if (take == cnt)        acc += (double)m.x;        // fully taken
        else if (take > 0)    { s_bb = i; s_take = take; } // unique boundary
    }
    __syncthreads();

    if (s_bb >= 0) {
        const float* cb = g_contrib + s_bb * RPT;
        for (int i = tid; i < s_take; i += FTPB) acc += (double)cb[i];
    }

#pragma unroll
    for (int o = 16; o > 0; o >>= 1)
        acc += __shfl_down_sync(0xffffffffu, acc, o);
    __shared__ double sd[FTPB / 32];
    if (lane == 0) sd[wid] = acc;
    __syncthreads();
    if (tid == 0) {
        double s = 0.0;
#pragma unroll
        for (int i = 0; i < FTPB / 32; i++) s += sd[i];
        out[0] = (float)s;
    }
}

// ---------------------------------------------------------------------------
extern "C" void kernel_launch(void* const* d_in, const int* in_sizes, int n_in,
                              void* d_out, int out_size) {
    const float* p = (const float*)d_in[0];
    const float* t = (const float*)d_in[1];

    const int nrows = in_sizes[0] / 30;
    const int nt    = (nrows + RPT - 1) / RPT;          // 6272

    const int smem_main = 2 * RPT * 30 * (int)sizeof(float);   // 30720
    cudaFuncSetAttribute(yolo_main,
                         cudaFuncAttributeMaxDynamicSharedMemorySize,
                         smem_main);

    const int smem_fin = 2 * nt * (int)sizeof(int);             // 50176
    cudaFuncSetAttribute(yolo_finalize,
                         cudaFuncAttributeMaxDynamicSharedMemorySize,
                         smem_fin);

    yolo_main<<<nt, TPB, smem_main>>>(p, t, nrows);

    cudaLaunchConfig_t cfg = {};
    cfg.gridDim          = dim3(1, 1, 1);
    cfg.blockDim         = dim3(FTPB, 1, 1);
    cfg.dynamicSmemBytes = smem_fin;
    cfg.stream           = 0;
    cudaLaunchAttribute attr[1];
    attr[0].id = cudaLaunchAttributeProgrammaticStreamSerialization;
    attr[0].val.programmaticStreamSerializationAllowed = 1;
    cfg.attrs    = attr;
    cfg.numAttrs = 1;
    float* outf = (float*)d_out;
    cudaLaunchKernelEx(&cfg, yolo_finalize, outf, nt);
}

// round 13
// speedup vs baseline: 1.1348x; 1.0449x over previous
#include <cuda_runtime.h>
#include <math.h>

// ---------------------------------------------------------------------------
// YoloV1Loss — R13 = R12 with 2x longer TMA bursts.
// R12 proved request-stream quality is the K1 lever (+4.1us from bulk TMA).
// Double it: 256 rows/block -> one 30720B contiguous bulk per array per block
// (3136 transfers instead of 6272), 256 thr, 61440B smem, 3 blocks/SM
// (shape validated by R6). nt halves -> K2 walk halves too.
// ---------------------------------------------------------------------------

#define TPB   256
#define RPT   256
#define MAXT  4096
#define NCLS  20
#define FTPB  1024
#define TILE_BYTES (RPT * 30 * 4)     // 30720 per array

__device__ float4 g_meta[MAXT];            // (csum, noobj, count, 0)
__device__ int    g_cnt[MAXT];
__device__ float  g_contrib[MAXT * RPT];   // rank-compacted per tile

// ---------------- K1: main pass ----------------
__global__ void __launch_bounds__(TPB) yolo_main(const float* __restrict__ p,
                                                 const float* __restrict__ t,
                                                 int nrows) {
    extern __shared__ float smem[];
    float* ps  = smem;                 // RPT*30 floats
    float* tsd = smem + RPT * 30;      // RPT*30 floats
    __shared__ __align__(8) unsigned long long mbar;
    __shared__ int   wtot[TPB / 32];
    __shared__ float wredN[TPB / 32];
    __shared__ float wredC[TPB / 32];

    const int tid  = threadIdx.x;
    const int bid  = blockIdx.x;
    const int row0 = bid * RPT;
    const int lane = tid & 31;
    const int wid  = tid >> 5;
    const int rows = min(RPT, nrows - row0);
    const size_t base = (size_t)row0 * 30;

    if (rows == RPT) {
        // ---- TMA bulk staging: 2 contiguous 30720B transfers ----
        const unsigned mb = (unsigned)__cvta_generic_to_shared(&mbar);
        const unsigned ap = (unsigned)__cvta_generic_to_shared(ps);
        const unsigned at = (unsigned)__cvta_generic_to_shared(tsd);
        if (tid == 0) {
            asm volatile("mbarrier.init.shared.b64 [%0], 1;"
                         :: "r"(mb) : "memory");
        }
        __syncthreads();
        if (tid == 0) {
            asm volatile("mbarrier.arrive.expect_tx.shared.b64 _, [%0], %1;"
                         :: "r"(mb), "r"(2 * TILE_BYTES) : "memory");
            asm volatile(
                "cp.async.bulk.shared::cta.global.mbarrier::complete_tx::bytes"
                " [%0], [%1], %2, [%3];"
                :: "r"(ap), "l"(p + base), "r"(TILE_BYTES), "r"(mb) : "memory");
            asm volatile(
                "cp.async.bulk.shared::cta.global.mbarrier::complete_tx::bytes"
                " [%0], [%1], %2, [%3];"
                :: "r"(at), "l"(t + base), "r"(TILE_BYTES), "r"(mb) : "memory");
        }
        // all threads wait for completion (phase 0), acquire semantics
        {
            unsigned done;
            asm volatile(
                "{\n\t.reg .pred pd;\n\t"
                "mbarrier.try_wait.parity.acquire.cta.shared::cta.b64 pd, [%1], 0;\n\t"
                "selp.b32 %0, 1, 0, pd;\n\t}"
                : "=r"(done) : "r"(mb) : "memory");
            while (!done) {
                asm volatile(
                    "{\n\t.reg .pred pd;\n\t"
                    "mbarrier.try_wait.parity.acquire.cta.shared::cta.b64 pd, [%1], 0, 0x989680;\n\t"
                    "selp.b32 %0, 1, 0, pd;\n\t}"
                    : "=r"(done) : "r"(mb) : "memory");
            }
        }
    } else {
        // ---- tail fallback: plain staged loads ----
        for (int i = tid; i < rows * 30; i += TPB) {
            ps[i]  = p[base + i];
            tsd[i] = t[base + i];
        }
    }
    __syncthreads();

    const bool inrange = (tid < rows);
    const float* pr = ps  + tid * 30;
    const float* tr = tsd + tid * 30;

    const float conf = inrange ? tr[4] : -1.0f;
    const bool  cm   = (conf == 1.0f);

    // in-block inclusive rank of coord rows
    const unsigned bal = __ballot_sync(0xffffffffu, cm);
    unsigned le_mask;
    asm("mov.u32 %0, %%lanemask_le;" : "=r"(le_mask));
    const int inc = __popc(bal & le_mask);
    if (lane == 31) wtot[wid] = __popc(bal);
    __syncthreads();
    int woff = 0, ctot = 0;
#pragma unroll
    for (int i = 0; i < TPB / 32; i++) {
        const int c = wtot[i];
        if (i < wid) woff += c;
        ctot += c;
    }

    // noobj term
    float nv = 0.0f;
    if (inrange && conf == 0.0f) {
        const float d0 = pr[4] - tr[4];
        const float d1 = pr[9] - tr[9];
        nv = 0.5f * (d0 * d0 + d1 * d1);
    }

    // coord term (global gate resolved in K2)
    float cv = 0.0f;
    if (cm) {
        const float C = 1.0f / 7.0f;
        const float tb0 = tr[0] * tr[0], tb1 = tr[1] * tr[1];
        const float tb2 = tr[2] * tr[2], tb3 = tr[3] * tr[3];
        const float tax = tb0 * C - tb2, tay = tb1 * C - tb3;
        const float tbx = tax * C + tb2, tby = tay * C + tb3;
        const float at2 = (tbx - tax) * (tby - tay);

        float iou0 = 0.0f, iou1 = 0.0f;
#pragma unroll
        for (int b = 0; b < 2; b++) {
            const float x = pr[b * 5 + 0], y = pr[b * 5 + 1];
            const float w = pr[b * 5 + 2], h = pr[b * 5 + 3];
            const float ax = x * C - w,  ay = y * C - h;
            const float bx = ax * C + w, by = ay * C + h;
            const float iw = fmaxf(fminf(bx, tbx) - fmaxf(ax, tax), 0.0f);
            const float ih = fmaxf(fminf(by, tby) - fmaxf(ay, tay), 0.0f);
            const float inter = iw * ih;
            const float ap2 = (bx - ax) * (by - ay);
            const float iou = inter / (ap2 + at2 - inter);
            if (b == 0) iou0 = iou; else iou1 = iou;
        }
        int idx;
        if (isnan(iou0))      idx = 0;   // numpy argmax: NaN wins, first occ.
        else if (isnan(iou1)) idx = 1;
        else                  idx = (iou1 > iou0) ? 1 : 0;

        const int ob = idx * 5;
        const float s0 = pr[ob + 0] - tr[0];
        const float s1 = pr[ob + 1] - tr[1];
        const float s2 = pr[ob + 2] - tr[2];
        const float s3 = pr[ob + 3] - tr[3];

        // class argmax from smem (first strict max) + paired p-select
        float best = tr[10];
        float clp  = pr[10];
#pragma unroll
        for (int j = 1; j < NCLS; j++) {
            const float v = tr[10 + j];
            const bool  u = (v > best);
            best = u ? v : best;
            clp  = u ? pr[10 + j] : clp;
        }
        const float clv = clp - 1.0f;

        cv = 5.0f * (s0 * s0 + s1 * s1 + s2 * s2 + s3 * s3 + 2.0f * clv * clv);
        g_contrib[bid * RPT + (woff + inc - 1)] = cv;
    }

    // block reductions: noobj + coord sums
#pragma unroll
    for (int o = 16; o > 0; o >>= 1) {
        nv += __shfl_down_sync(0xffffffffu, nv, o);
        cv += __shfl_down_sync(0xffffffffu, cv, o);
    }
    if (lane == 0) { wredN[wid] = nv; wredC[wid] = cv; }
    __syncthreads();
    if (tid == 0) {
        float sn = 0.0f, sc = 0.0f;
#pragma unroll
        for (int i = 0; i < TPB / 32; i++) { sn += wredN[i]; sc += wredC[i]; }
        g_meta[bid] = make_float4(sc, sn, __int_as_float(ctot), 0.0f);
        g_cnt[bid]  = ctot;
    }
    __syncthreads();

    // PDL trigger (neutral but harmless)
    asm volatile("griddepcontrol.launch_dependents;" ::: "memory");
}

// ---------------- K2: finalize (PDL-gated, single block) ----------------
__global__ void __launch_bounds__(FTPB) yolo_finalize(float* __restrict__ out,
                                                      int nt) {
    asm volatile("griddepcontrol.wait;" ::: "memory");

    extern __shared__ int ismem[];
    int* scnt = ismem;          // nt ints
    int* spre = ismem + nt;     // nt ints

    const int tid  = threadIdx.x;
    const int lane = tid & 31;
    const int wid  = tid >> 5;

    for (int i = tid; i < nt; i += FTPB) scnt[i] = g_cnt[i];
    __syncthreads();

    const int CH = (nt + FTPB - 1) / FTPB;
    const int i0 = tid * CH;
    int lsum = 0;
    for (int k = 0; k < CH; k++) {
        const int i = i0 + k;
        if (i < nt) lsum += scnt[i];
    }
    int incs = lsum;
#pragma unroll
    for (int o = 1; o < 32; o <<= 1) {
        const int x = __shfl_up_sync(0xffffffffu, incs, o);
        if (lane >= o) incs += x;
    }
    const int ex = incs - lsum;

    __shared__ int ws[FTPB / 32];
    __shared__ int wsx[FTPB / 32 + 1];
    __shared__ int s_bb, s_take;
    if (tid == 0) { s_bb = -1; s_take = 0; }
    if (lane == 31) ws[wid] = incs;
    __syncthreads();
    if (wid == 0) {
        int v = ws[lane];
#pragma unroll
        for (int o = 1; o < 32; o <<= 1) {
            const int x = __shfl_up_sync(0xffffffffu, v, o);
            if (lane >= o) v += x;
        }
        wsx[lane + 1] = v;
        if (lane == 0) wsx[0] = 0;
    }
    __syncthreads();
    const int half = wsx[FTPB / 32] >> 1;      // n_obj // 2

    {
        int pre = wsx[wid] + ex;
        for (int k = 0; k < CH; k++) {
            const int i = i0 + k;
            if (i < nt) { spre[i] = pre; pre += scnt[i]; }
        }
    }
    __syncthreads();

    double acc = 0.0;
    for (int i = tid; i < nt; i += FTPB) {
        const float4 m   = g_meta[i];
        const int    cnt = scnt[i];
        const int    pre = spre[i];
        acc += (double)m.y;                                // noobj always
        const int take = min(cnt, max(0, half - pre));
        if (take == cnt)        acc += (double)m.x;        // fully taken
        else if (take > 0)    { s_bb = i; s_take = take; } // unique boundary
    }
    __syncthreads();

    if (s_bb >= 0) {
        const float* cb = g_contrib + s_bb * RPT;
        for (int i = tid; i < s_take; i += FTPB) acc += (double)cb[i];
    }

#pragma unroll
    for (int o = 16; o > 0; o >>= 1)
        acc += __shfl_down_sync(0xffffffffu, acc, o);
    __shared__ double sd[FTPB / 32];
    if (lane == 0) sd[wid] = acc;
    __syncthreads();
    if (tid == 0) {
        double s = 0.0;
#pragma unroll
        for (int i = 0; i < FTPB / 32; i++) s += sd[i];
        out[0] = (float)s;
    }
}

// ---------------------------------------------------------------------------
extern "C" void kernel_launch(void* const* d_in, const int* in_sizes, int n_in,
                              void* d_out, int out_size) {
    const float* p = (const float*)d_in[0];
    const float* t = (const float*)d_in[1];

    const int nrows = in_sizes[0] / 30;
    const int nt    = (nrows + RPT - 1) / RPT;          // 3136

    const int smem_main = 2 * RPT * 30 * (int)sizeof(float);   // 61440
    cudaFuncSetAttribute(yolo_main,
                         cudaFuncAttributeMaxDynamicSharedMemorySize,
                         smem_main);

    const int smem_fin = 2 * nt * (int)sizeof(int);             // 25088
    cudaFuncSetAttribute(yolo_finalize,
                         cudaFuncAttributeMaxDynamicSharedMemorySize,
                         smem_fin);

    yolo_main<<<nt, TPB, smem_main>>>(p, t, nrows);

    cudaLaunchConfig_t cfg = {};
    cfg.gridDim          = dim3(1, 1, 1);
    cfg.blockDim         = dim3(FTPB, 1, 1);
    cfg.dynamicSmemBytes = smem_fin;
    cfg.stream           = 0;
    cudaLaunchAttribute attr[1];
    attr[0].id = cudaLaunchAttributeProgrammaticStreamSerialization;
    attr[0].val.programmaticStreamSerializationAllowed = 1;
    cfg.attrs    = attr;
    cfg.numAttrs = 1;
    float* outf = (float*)d_out;
    cudaLaunchKernelEx(&cfg, yolo_finalize, outf, nt);
}